// round 7
// baseline (speedup 1.0000x reference)
#include <cuda_runtime.h>
#include <cstdint>

// WeightedAggregator: out[b, :] = sum_k (w[b,k] / sum_j w[b,j]) * features[idx[b,k], :]
// B = 50000, K = 16, D = 128 (fp32). One warp per output row; one float4 per lane.
// neigh_idx is int32 (JAX demotes int64 without x64 mode).
//
// R7: index-windowed two-phase gather. All warps first process neighbors with
// idx < N/2, then idx >= N/2. This shrinks the instantaneous working set to
// ~128 MB (fits the 126 MB L2), so re-references hit L2 instead of DRAM.
// Output stores use evict_first (cache_hint form) so the 26 MB of write-once
// data doesn't evict the feature window. Accumulator stays in registers
// across phases -> no extra output traffic.

#define K_NEIGH 16
#define FEAT_D 128

__device__ __forceinline__ uint64_t policy_evict_first() {
    uint64_t p;
    asm("createpolicy.fractional.L2::evict_first.b64 %0, 1.0;" : "=l"(p));
    return p;
}

__device__ __forceinline__ void stg_hint(float4* p, float4 v, uint64_t pol) {
    asm volatile("st.global.L2::cache_hint.v4.f32 [%0], {%1,%2,%3,%4}, %5;"
                 :: "l"(p), "f"(v.x), "f"(v.y), "f"(v.z), "f"(v.w), "l"(pol)
                 : "memory");
}

__global__ __launch_bounds__(256)
void weighted_agg_kernel(const float* __restrict__ features,
                         const float* __restrict__ neigh_w,
                         const int* __restrict__ neigh_idx,
                         float* __restrict__ out,
                         int B, int mid)
{
    const int gtid = blockIdx.x * blockDim.x + threadIdx.x;
    const int row  = gtid >> 5;          // warp id = output row
    const int lane = threadIdx.x & 31;
    if (row >= B) return;

    const uint64_t pol_first = policy_evict_first();

    // Lanes 0..15 hold this row's weight + index; others hold 0.
    float w  = 0.0f;
    int   ix = 0;
    if (lane < K_NEIGH) {
        w  = neigh_w  [row * K_NEIGH + lane];
        ix = neigh_idx[row * K_NEIGH + lane];
    }

    // Warp-wide sum of weights (lanes >= 16 contribute 0).
    float s = w;
    #pragma unroll
    for (int off = 16; off > 0; off >>= 1)
        s += __shfl_xor_sync(0xffffffffu, s, off);
    const float inv = 1.0f / s;

    const float4* __restrict__ feat4 = (const float4*)features;

    // Broadcast all 16 (idx, weight) pairs once.
    int   ik[K_NEIGH];
    float wk[K_NEIGH];
    #pragma unroll
    for (int k = 0; k < K_NEIGH; k++) {
        ik[k] = __shfl_sync(0xffffffffu, ix, k);
        wk[k] = __shfl_sync(0xffffffffu, w, k);
    }

    // Two-phase gather: phase 0 = idx < mid (lower half of table),
    // phase 1 = idx >= mid. Warp-uniform predicates -> no divergence.
    float4 a0 = make_float4(0.f, 0.f, 0.f, 0.f);
    float4 a1 = make_float4(0.f, 0.f, 0.f, 0.f);

    #pragma unroll
    for (int p = 0; p < 2; p++) {
        // Issue all loads for this phase first (front-batched -> high MLP).
        float4 f[K_NEIGH];
        bool   m[K_NEIGH];
        #pragma unroll
        for (int k = 0; k < K_NEIGH; k++) {
            m[k] = (ik[k] < mid) == (p == 0);
            if (m[k])
                f[k] = __ldg(feat4 + (long long)ik[k] * (FEAT_D / 4) + lane);
        }
        // Then accumulate (two independent FFMA chains).
        #pragma unroll
        for (int k = 0; k < K_NEIGH; k += 2) {
            if (m[k]) {
                a0.x += wk[k] * f[k].x;  a0.y += wk[k] * f[k].y;
                a0.z += wk[k] * f[k].z;  a0.w += wk[k] * f[k].w;
            }
            if (m[k + 1]) {
                a1.x += wk[k + 1] * f[k + 1].x;  a1.y += wk[k + 1] * f[k + 1].y;
                a1.z += wk[k + 1] * f[k + 1].z;  a1.w += wk[k + 1] * f[k + 1].w;
            }
        }
    }

    float4 r;
    r.x = (a0.x + a1.x) * inv;
    r.y = (a0.y + a1.y) * inv;
    r.z = (a0.z + a1.z) * inv;
    r.w = (a0.w + a1.w) * inv;

    stg_hint((float4*)out + (long long)row * (FEAT_D / 4) + lane, r, pol_first);
}

extern "C" void kernel_launch(void* const* d_in, const int* in_sizes, int n_in,
                              void* d_out, int out_size)
{
    const float* features  = (const float*)d_in[0];   // [N_NODES, 128] fp32
    const float* neigh_w   = (const float*)d_in[1];   // [B, 16] fp32
    const int*   neigh_idx = (const int*)d_in[2];     // [B, 16] int32
    float*       out       = (float*)d_out;           // [B, 128] fp32

    const int B = in_sizes[1] / K_NEIGH;        // 50000
    const int N = in_sizes[0] / FEAT_D;         // 500000
    const int mid = N / 2;                      // 128 MB window boundary

    const int threads = 256;                    // 8 warps/block -> 8 rows/block
    const int rows_per_block = threads / 32;
    const int blocks = (B + rows_per_block - 1) / rows_per_block;

    weighted_agg_kernel<<<blocks, threads>>>(features, neigh_w, neigh_idx, out, B, mid);
}

// round 8
// speedup vs baseline: 1.5198x; 1.5198x over previous
#include <cuda_runtime.h>
#include <cstdint>

// WeightedAggregator: out[b,:] = sum_k (w[b,k]/sum_j w[b,j]) * features[idx[b,k],:]
// B = 50000, K = 16, D = 128 (fp32). neigh_idx is int32 (JAX demotes int64).
//
// R8: TWO-KERNEL index-windowed gather. Phase 0 gathers only rows with
// idx < mid (lower 128 MB of the table), phase 1 gathers idx >= mid.
// The launch boundary gives chip-wide phase coherence: each phase's touched
// set (~102 MB of unique rows) fits the 126 MB L2, so every repeat draw hits
// L2. Partial sums round-trip through d_out (unnormalized after phase 0,
// normalized at the end of phase 1) with evict_first so they don't evict the
// feature window. Each kernel keeps the R4 register footprint (~34 regs).

#define K_NEIGH 16
#define FEAT_D 128

__device__ __forceinline__ uint64_t policy_evict_first() {
    uint64_t p;
    asm("createpolicy.fractional.L2::evict_first.b64 %0, 1.0;" : "=l"(p));
    return p;
}

__device__ __forceinline__ void stg_hint(float4* p, float4 v, uint64_t pol) {
    asm volatile("st.global.L2::cache_hint.v4.f32 [%0], {%1,%2,%3,%4}, %5;"
                 :: "l"(p), "f"(v.x), "f"(v.y), "f"(v.z), "f"(v.w), "l"(pol)
                 : "memory");
}

__device__ __forceinline__ float4 ldg_hint_first(const float4* p, uint64_t pol) {
    float4 v;
    asm("ld.global.nc.L2::cache_hint.v4.f32 {%0,%1,%2,%3}, [%4], %5;"
        : "=f"(v.x), "=f"(v.y), "=f"(v.z), "=f"(v.w)
        : "l"(p), "l"(pol));
    return v;
}

template <bool FIRST>
__global__ __launch_bounds__(256)
void weighted_agg_phase(const float* __restrict__ features,
                        const float* __restrict__ neigh_w,
                        const int* __restrict__ neigh_idx,
                        float* __restrict__ out,
                        int B, int lo, int hi)
{
    const int gtid = blockIdx.x * blockDim.x + threadIdx.x;
    const int row  = gtid >> 5;          // warp id = output row
    const int lane = threadIdx.x & 31;
    if (row >= B) return;

    const uint64_t pol_first = policy_evict_first();

    // Lanes 0..15 hold this row's weight + index; others hold 0.
    float w  = 0.0f;
    int   ix = 0;
    if (lane < K_NEIGH) {
        w  = neigh_w  [row * K_NEIGH + lane];
        ix = neigh_idx[row * K_NEIGH + lane];
    }

    float4* outp = (float4*)out + (long long)row * (FEAT_D / 4) + lane;

    // Start the partial-sum load early (phase 1 only) to overlap with shuffles.
    float4 a0 = make_float4(0.f, 0.f, 0.f, 0.f);
    float4 a1 = make_float4(0.f, 0.f, 0.f, 0.f);
    if (!FIRST)
        a0 = ldg_hint_first((const float4*)outp, pol_first);

    // Warp-wide weight sum (lanes >= 16 contribute 0).
    float s = w;
    #pragma unroll
    for (int off = 16; off > 0; off >>= 1)
        s += __shfl_xor_sync(0xffffffffu, s, off);
    const float inv = 1.0f / s;

    const float4* __restrict__ feat4 = (const float4*)features;

    // Predicated gather+accumulate, two independent FFMA chains.
    // Branch condition is warp-uniform (broadcast index) -> no divergence.
    #pragma unroll
    for (int k = 0; k < K_NEIGH; k += 2) {
        const int   i0 = __shfl_sync(0xffffffffu, ix, k);
        const int   i1 = __shfl_sync(0xffffffffu, ix, k + 1);
        const float w0 = __shfl_sync(0xffffffffu, w, k);
        const float w1 = __shfl_sync(0xffffffffu, w, k + 1);
        if (i0 >= lo && i0 < hi) {
            const float4 f = __ldg(feat4 + (long long)i0 * (FEAT_D / 4) + lane);
            a0.x += w0 * f.x;  a0.y += w0 * f.y;
            a0.z += w0 * f.z;  a0.w += w0 * f.w;
        }
        if (i1 >= lo && i1 < hi) {
            const float4 f = __ldg(feat4 + (long long)i1 * (FEAT_D / 4) + lane);
            a1.x += w1 * f.x;  a1.y += w1 * f.y;
            a1.z += w1 * f.z;  a1.w += w1 * f.w;
        }
    }

    float4 r;
    if (FIRST) {   // store unnormalized partial
        r.x = a0.x + a1.x;  r.y = a0.y + a1.y;
        r.z = a0.z + a1.z;  r.w = a0.w + a1.w;
    } else {       // partial (in a0) + this half, normalized
        r.x = (a0.x + a1.x) * inv;
        r.y = (a0.y + a1.y) * inv;
        r.z = (a0.z + a1.z) * inv;
        r.w = (a0.w + a1.w) * inv;
    }
    stg_hint(outp, r, pol_first);
}

extern "C" void kernel_launch(void* const* d_in, const int* in_sizes, int n_in,
                              void* d_out, int out_size)
{
    const float* features  = (const float*)d_in[0];   // [N_NODES, 128] fp32
    const float* neigh_w   = (const float*)d_in[1];   // [B, 16] fp32
    const int*   neigh_idx = (const int*)d_in[2];     // [B, 16] int32
    float*       out       = (float*)d_out;           // [B, 128] fp32

    const int B   = in_sizes[1] / K_NEIGH;   // 50000
    const int N   = in_sizes[0] / FEAT_D;    // 500000
    const int mid = N / 2;

    const int threads = 256;                 // 8 warps/block -> 8 rows/block
    const int rows_per_block = threads / 32;
    const int blocks = (B + rows_per_block - 1) / rows_per_block;

    weighted_agg_phase<true ><<<blocks, threads>>>(features, neigh_w, neigh_idx,
                                                   out, B, 0, mid);
    weighted_agg_phase<false><<<blocks, threads>>>(features, neigh_w, neigh_idx,
                                                   out, B, mid, N);
}

// round 9
// speedup vs baseline: 1.8292x; 1.2036x over previous
#include <cuda_runtime.h>

// WeightedAggregator: out[b,:] = sum_k (w[b,k]/sum_j w[b,j]) * features[idx[b,k],:]
// B = 50000, K = 16, D = 128 (fp32). One warp per output row; one float4 per lane.
// neigh_idx is int32 (JAX demotes int64 without x64 mode).
//
// R9: baseline R4 structure + enforced MLP=4 gather groups. Loads go through
// inline-asm ld.global.nc.v4.f32 so ptxas cannot sink them into the FMA chain
// (R4 compiled to 34 regs = serialized loads, MLP~2). Four float4 loads are
// issued back-to-back per group, then consumed. ~48 regs -> occupancy
// unchanged, per-warp outstanding lines ~2x.

#define K_NEIGH 16
#define FEAT_D 128

__device__ __forceinline__ float4 ldg_nc_v4(const float4* p) {
    float4 v;
    asm("ld.global.nc.v4.f32 {%0,%1,%2,%3}, [%4];"
        : "=f"(v.x), "=f"(v.y), "=f"(v.z), "=f"(v.w)
        : "l"(p));
    return v;
}

__global__ __launch_bounds__(256)
void weighted_agg_kernel(const float* __restrict__ features,
                         const float* __restrict__ neigh_w,
                         const int* __restrict__ neigh_idx,
                         float* __restrict__ out,
                         int B)
{
    const int gtid = blockIdx.x * blockDim.x + threadIdx.x;
    const int row  = gtid >> 5;          // warp id = output row
    const int lane = threadIdx.x & 31;
    if (row >= B) return;

    // Lanes 0..15 hold this row's weight + index; others hold 0.
    float w  = 0.0f;
    int   ix = 0;
    if (lane < K_NEIGH) {
        w  = neigh_w  [row * K_NEIGH + lane];
        ix = neigh_idx[row * K_NEIGH + lane];
    }

    // Warp-wide weight sum (lanes >= 16 contribute 0).
    float s = w;
    #pragma unroll
    for (int off = 16; off > 0; off >>= 1)
        s += __shfl_xor_sync(0xffffffffu, s, off);
    const float inv = 1.0f / s;

    const float4* __restrict__ feat4 = (const float4*)features;

    float4 a0 = make_float4(0.f, 0.f, 0.f, 0.f);
    float4 a1 = make_float4(0.f, 0.f, 0.f, 0.f);

    // 4 groups of 4 gathers. Within a group: broadcast 4 indices, issue 4
    // independent LDG.128 (asm keeps them front-batched), then 4 weighted
    // accumulates split over two FFMA chains.
    #pragma unroll
    for (int g = 0; g < K_NEIGH; g += 4) {
        const int i0 = __shfl_sync(0xffffffffu, ix, g + 0);
        const int i1 = __shfl_sync(0xffffffffu, ix, g + 1);
        const int i2 = __shfl_sync(0xffffffffu, ix, g + 2);
        const int i3 = __shfl_sync(0xffffffffu, ix, g + 3);

        const float4 f0 = ldg_nc_v4(feat4 + (long long)i0 * (FEAT_D / 4) + lane);
        const float4 f1 = ldg_nc_v4(feat4 + (long long)i1 * (FEAT_D / 4) + lane);
        const float4 f2 = ldg_nc_v4(feat4 + (long long)i2 * (FEAT_D / 4) + lane);
        const float4 f3 = ldg_nc_v4(feat4 + (long long)i3 * (FEAT_D / 4) + lane);

        const float w0 = __shfl_sync(0xffffffffu, w, g + 0);
        const float w1 = __shfl_sync(0xffffffffu, w, g + 1);
        const float w2 = __shfl_sync(0xffffffffu, w, g + 2);
        const float w3 = __shfl_sync(0xffffffffu, w, g + 3);

        a0.x += w0 * f0.x;  a0.y += w0 * f0.y;  a0.z += w0 * f0.z;  a0.w += w0 * f0.w;
        a1.x += w1 * f1.x;  a1.y += w1 * f1.y;  a1.z += w1 * f1.z;  a1.w += w1 * f1.w;
        a0.x += w2 * f2.x;  a0.y += w2 * f2.y;  a0.z += w2 * f2.z;  a0.w += w2 * f2.w;
        a1.x += w3 * f3.x;  a1.y += w3 * f3.y;  a1.z += w3 * f3.z;  a1.w += w3 * f3.w;
    }

    float4 r;
    r.x = (a0.x + a1.x) * inv;
    r.y = (a0.y + a1.y) * inv;
    r.z = (a0.z + a1.z) * inv;
    r.w = (a0.w + a1.w) * inv;

    ((float4*)out)[(long long)row * (FEAT_D / 4) + lane] = r;
}

extern "C" void kernel_launch(void* const* d_in, const int* in_sizes, int n_in,
                              void* d_out, int out_size)
{
    const float* features  = (const float*)d_in[0];   // [N_NODES, 128] fp32
    const float* neigh_w   = (const float*)d_in[1];   // [B, 16] fp32
    const int*   neigh_idx = (const int*)d_in[2];     // [B, 16] int32
    float*       out       = (float*)d_out;           // [B, 128] fp32

    const int B = in_sizes[1] / K_NEIGH;   // 50000

    const int threads = 256;               // 8 warps/block -> 8 rows/block
    const int rows_per_block = threads / 32;
    const int blocks = (B + rows_per_block - 1) / rows_per_block;

    weighted_agg_kernel<<<blocks, threads>>>(features, neigh_w, neigh_idx, out, B);
}